// round 1
// baseline (speedup 1.0000x reference)
#include <cuda_runtime.h>
#include <cuda_bf16.h>
#include <math.h>

#define BS   8
#define SEQ  512
#define C    512
#define NC   5
#define H    768
#define W    768
#define NTOK (BS*SEQ)          // 4096

// Scratch (no allocations allowed): label map + per-token partials
__device__ unsigned char g_lab[BS * H * W];       // 4.72 MB
__device__ float         g_nll[NTOK];
__device__ int           g_msk[NTOK];

// ---------------------------------------------------------------------------
// Kernel 1: per-pixel argmax over NC=5 channel planes -> uint8 labels
// Vectorized: each thread handles 4 consecutive pixels (float4 per plane).
// ---------------------------------------------------------------------------
__global__ void argmax_labels_kernel(const float* __restrict__ cl) {
    const int n4 = BS * H * W / 4;                // 1,179,648 groups
    int g = blockIdx.x * blockDim.x + threadIdx.x;
    if (g >= n4) return;

    // group -> (b, pixel4)
    const int pix_per_img4 = H * W / 4;           // 147,456
    int b = g / pix_per_img4;
    int p4 = g - b * pix_per_img4;                // group index within image
    size_t base = (size_t)b * NC * H * W + (size_t)p4 * 4;

    float best0, best1, best2, best3;
    int   lab0 = 0, lab1 = 0, lab2 = 0, lab3 = 0;

    {
        float4 v = *reinterpret_cast<const float4*>(cl + base);
        best0 = v.x; best1 = v.y; best2 = v.z; best3 = v.w;
    }
#pragma unroll
    for (int c = 1; c < NC; ++c) {
        float4 v = *reinterpret_cast<const float4*>(cl + base + (size_t)c * H * W);
        if (v.x > best0) { best0 = v.x; lab0 = c; }
        if (v.y > best1) { best1 = v.y; lab1 = c; }
        if (v.z > best2) { best2 = v.z; lab2 = c; }
        if (v.w > best3) { best3 = v.w; lab3 = c; }
    }
    uchar4 out;
    out.x = (unsigned char)lab0; out.y = (unsigned char)lab1;
    out.z = (unsigned char)lab2; out.w = (unsigned char)lab3;
    *reinterpret_cast<uchar4*>(g_lab + (size_t)b * H * W + (size_t)p4 * 4) = out;
}

// ---------------------------------------------------------------------------
// Kernel 2: one warp per token.
//  - logits[5] = fuse[b,s,:] . Wc[c,:] + bc[c]   (Wc staged in shared)
//  - box histogram over uint8 label map (direct count, no integral image)
//  - first-max argmax (matches jnp.argmax / bincount().argmax() tiebreak)
//  - masked NLL written to per-token scratch
// ---------------------------------------------------------------------------
__global__ void token_kernel(const float* __restrict__ fuse,
                             const float* __restrict__ Wc,
                             const float* __restrict__ bc,
                             const int*   __restrict__ coords,
                             const int*   __restrict__ mask) {
    __shared__ float sW[NC * C];                  // 10 KB
    for (int i = threadIdx.x; i < NC * C; i += blockDim.x)
        sW[i] = Wc[i];
    __syncthreads();

    const int warp = threadIdx.x >> 5;
    const int lane = threadIdx.x & 31;
    const int warps_per_block = blockDim.x >> 5;
    int t = blockIdx.x * warps_per_block + warp;  // token id
    if (t >= NTOK) return;

    const int b = t / SEQ;

    // ---- logits ----
    const float* fe = fuse + (size_t)t * C;
    float acc0 = 0.f, acc1 = 0.f, acc2 = 0.f, acc3 = 0.f, acc4 = 0.f;
    for (int k = lane; k < C; k += 32) {
        float e = fe[k];
        acc0 += e * sW[0 * C + k];
        acc1 += e * sW[1 * C + k];
        acc2 += e * sW[2 * C + k];
        acc3 += e * sW[3 * C + k];
        acc4 += e * sW[4 * C + k];
    }
#pragma unroll
    for (int off = 16; off; off >>= 1) {
        acc0 += __shfl_xor_sync(0xffffffffu, acc0, off);
        acc1 += __shfl_xor_sync(0xffffffffu, acc1, off);
        acc2 += __shfl_xor_sync(0xffffffffu, acc2, off);
        acc3 += __shfl_xor_sync(0xffffffffu, acc3, off);
        acc4 += __shfl_xor_sync(0xffffffffu, acc4, off);
    }

    // ---- box histogram ----
    int x0 = coords[t * 4 + 0];
    int y0 = coords[t * 4 + 1];
    int x1 = coords[t * 4 + 2];
    int y1 = coords[t * 4 + 3];
    if (y1 == y0) y1 = y0 + 1;
    if (x1 == x0) x1 = x0 + 1;

    int c0 = 0, c1 = 0, c2 = 0, c3 = 0, c4 = 0;
    const unsigned char* labb = g_lab + (size_t)b * H * W;
    for (int y = y0; y < y1; ++y) {
        const unsigned char* row = labb + (size_t)y * W;
        for (int x = x0 + lane; x < x1; x += 32) {
            int l = row[x];
            c0 += (l == 0); c1 += (l == 1); c2 += (l == 2);
            c3 += (l == 3); c4 += (l == 4);
        }
    }
    c0 = __reduce_add_sync(0xffffffffu, c0);
    c1 = __reduce_add_sync(0xffffffffu, c1);
    c2 = __reduce_add_sync(0xffffffffu, c2);
    c3 = __reduce_add_sync(0xffffffffu, c3);
    c4 = __reduce_add_sync(0xffffffffu, c4);

    if (lane == 0) {
        // first-max argmax over counts
        int maj = 0, bestc = c0;
        if (c1 > bestc) { bestc = c1; maj = 1; }
        if (c2 > bestc) { bestc = c2; maj = 2; }
        if (c3 > bestc) { bestc = c3; maj = 3; }
        if (c4 > bestc) { bestc = c4; maj = 4; }

        float lg[NC];
        lg[0] = acc0 + bc[0]; lg[1] = acc1 + bc[1]; lg[2] = acc2 + bc[2];
        lg[3] = acc3 + bc[3]; lg[4] = acc4 + bc[4];

        float mx = lg[0];
#pragma unroll
        for (int c = 1; c < NC; ++c) mx = fmaxf(mx, lg[c]);
        float se = 0.f;
#pragma unroll
        for (int c = 0; c < NC; ++c) se += expf(lg[c] - mx);
        float nll = -(lg[maj] - mx - logf(se));

        int m = (mask[t] == 1) ? 1 : 0;
        g_nll[t] = nll * (float)m;
        g_msk[t] = m;
    }
}

// ---------------------------------------------------------------------------
// Kernel 3: deterministic single-block reduction -> scalar
// ---------------------------------------------------------------------------
__global__ void reduce_kernel(float* __restrict__ out) {
    __shared__ float sf[1024];
    __shared__ int   si[1024];
    int t = threadIdx.x;
    float a = g_nll[t] + g_nll[t + 1024] + g_nll[t + 2048] + g_nll[t + 3072];
    int   m = g_msk[t] + g_msk[t + 1024] + g_msk[t + 2048] + g_msk[t + 3072];
    sf[t] = a; si[t] = m;
    __syncthreads();
#pragma unroll
    for (int s = 512; s > 0; s >>= 1) {
        if (t < s) { sf[t] += sf[t + s]; si[t] += si[t + s]; }
        __syncthreads();
    }
    if (t == 0) out[0] = sf[0] / (float)si[0];
}

extern "C" void kernel_launch(void* const* d_in, const int* in_sizes, int n_in,
                              void* d_out, int out_size) {
    const float* fuse   = (const float*)d_in[0];   // [8,512,512]
    const float* cl     = (const float*)d_in[1];   // [8,5,768,768]
    const float* Wc     = (const float*)d_in[2];   // [5,512]
    const float* bc     = (const float*)d_in[3];   // [5]
    const int*   coords = (const int*)d_in[4];     // [8,512,4]
    const int*   mask   = (const int*)d_in[5];     // [8,512]
    float* out = (float*)d_out;

    // Kernel 1: label map
    {
        int n4 = BS * H * W / 4;
        int threads = 256;
        int blocks = (n4 + threads - 1) / threads;
        argmax_labels_kernel<<<blocks, threads>>>(cl);
    }
    // Kernel 2: per-token logits + box majority + NLL
    {
        int threads = 128;                       // 4 warps = 4 tokens / block
        int blocks = NTOK / 4;                   // 1024
        token_kernel<<<blocks, threads>>>(fuse, Wc, bc, coords, mask);
    }
    // Kernel 3: final scalar
    reduce_kernel<<<1, 1024>>>(out);
}